// round 11
// baseline (speedup 1.0000x reference)
#include <cuda_runtime.h>
#include <cuda_fp16.h>
#include <math.h>
#include <stdint.h>

#define T_TOK 1024
#define DHID 1024
#define NE 16
#define TOPK 8
#define NI 1024
#define ROUTE_SCALE 2.826f

#define ROW_TILES 88
#define ROWS_CAP (ROW_TILES * 128)
#define WSZ (1u << 20)

#define SW(o) ((o) ^ (((o) >> 3) & 0x70))

// ---------------- scratch ----------------
__device__ __half g_xh[T_TOK * DHID], g_xl[T_TOK * DHID];
__device__ __half g_wgh[17 * WSZ], g_wgl[17 * WSZ];
__device__ __half g_wuh[17 * WSZ], g_wul[17 * WSZ];
__device__ __half g_wdh[17 * WSZ], g_wdl[17 * WSZ];
__device__ __half g_Hh[(size_t)ROWS_CAP * NI];
__device__ float  g_Y[(size_t)ROWS_CAP * DHID];
__device__ int    g_row_token[ROWS_CAP];
__device__ float  g_row_wt[ROWS_CAP];
__device__ int    g_tile_expert[ROW_TILES];
__device__ int    g_token_rows[T_TOK * 9];
__device__ int    g_counts[NE + 1];
__device__ int    g_fill[NE + 1];
__device__ int    g_offsets[NE + 2];
__device__ int    g_topk_idx[T_TOK * TOPK];
__device__ float  g_topk_wt[T_TOK * TOPK];

// ---------------- helpers ----------------
__device__ __forceinline__ uint32_t smem_u32(const void* p) {
    uint32_t a;
    asm("{ .reg .u64 t; cvta.to.shared.u64 t, %1; cvt.u32.u64 %0, t; }" : "=r"(a) : "l"(p));
    return a;
}
__device__ __forceinline__ void ldsm4(uint32_t (&r)[4], uint32_t addr) {
    asm volatile("ldmatrix.sync.aligned.m8n8.x4.shared.b16 {%0,%1,%2,%3}, [%4];"
                 : "=r"(r[0]), "=r"(r[1]), "=r"(r[2]), "=r"(r[3]) : "r"(addr));
}
__device__ __forceinline__ void mma_f16(float (&d)[4], const uint32_t (&a)[4],
                                        uint32_t b0, uint32_t b1) {
    asm volatile("mma.sync.aligned.m16n8k16.row.col.f32.f16.f16.f32 "
                 "{%0,%1,%2,%3}, {%4,%5,%6,%7}, {%8,%9}, {%0,%1,%2,%3};"
                 : "+f"(d[0]), "+f"(d[1]), "+f"(d[2]), "+f"(d[3])
                 : "r"(a[0]), "r"(a[1]), "r"(a[2]), "r"(a[3]), "r"(b0), "r"(b1));
}
__device__ __forceinline__ void cpa16(uint32_t dst, const void* src) {
    asm volatile("cp.async.cg.shared.global [%0], [%1], 16;" :: "r"(dst), "l"(src));
}
#define CPA_COMMIT() asm volatile("cp.async.commit_group;" ::: "memory")
#define CPA_WAIT1()  asm volatile("cp.async.wait_group 1;" ::: "memory")
#define CPA_WAIT0()  asm volatile("cp.async.wait_group 0;" ::: "memory")

// ---------------- L0: split + init ----------------
struct SplitArgs {
    const float* src[7];
    __half* hi[7];
    __half* lo[7];
    int blk_end[7];
    int split_blocks;
};
__global__ void __launch_bounds__(256) k_split_all(SplitArgs a) {
    int b = blockIdx.x;
    if (b >= a.split_blocks) {
        int i = (b - a.split_blocks) * 256 + threadIdx.x;
        if (i < ROWS_CAP) { g_row_token[i] = 0; g_row_wt[i] = 0.f; }
        if (i < ROW_TILES) g_tile_expert[i] = -1;
        if (i < NE + 1) { g_counts[i] = 0; g_fill[i] = 0; }
        return;
    }
    int s = 0;
    while (b >= a.blk_end[s]) s++;
    int base = s ? a.blk_end[s - 1] : 0;
    size_t i = ((size_t)(b - base) * 256 + threadIdx.x) << 2;
    float4 v = *(const float4*)(a.src[s] + i);
    __half h0 = __float2half(v.x), h1 = __float2half(v.y);
    __half h2 = __float2half(v.z), h3 = __float2half(v.w);
    uint2 hp;
    hp.x = (uint32_t)__half_as_ushort(h0) | ((uint32_t)__half_as_ushort(h1) << 16);
    hp.y = (uint32_t)__half_as_ushort(h2) | ((uint32_t)__half_as_ushort(h3) << 16);
    *(uint2*)&a.hi[s][i] = hp;
    __half l0 = __float2half(v.x - __half2float(h0));
    __half l1 = __float2half(v.y - __half2float(h1));
    __half l2 = __float2half(v.z - __half2float(h2));
    __half l3 = __float2half(v.w - __half2float(h3));
    uint2 lp;
    lp.x = (uint32_t)__half_as_ushort(l0) | ((uint32_t)__half_as_ushort(l1) << 16);
    lp.y = (uint32_t)__half_as_ushort(l2) | ((uint32_t)__half_as_ushort(l3) << 16);
    *(uint2*)&a.lo[s][i] = lp;
}

// ---------------- L1: routing ----------------
__global__ void __launch_bounds__(128) k_route(const float* __restrict__ x,
                                               const float* __restrict__ gw,
                                               const float* __restrict__ bias) {
    __shared__ float xs[DHID];
    __shared__ float gates[NE];
    int t = blockIdx.x, tid = threadIdx.x;
    for (int i = tid; i < DHID; i += 128) xs[i] = x[(size_t)t * DHID + i];
    __syncthreads();
    int e = tid >> 3, p = tid & 7;
    const float* w = gw + e * DHID + p * 128;
    const float* xv = xs + p * 128;
    float s = 0.f;
#pragma unroll 8
    for (int d = 0; d < 128; d++) s += xv[d] * w[d];
    s += __shfl_down_sync(0xffffffffu, s, 4, 8);
    s += __shfl_down_sync(0xffffffffu, s, 2, 8);
    s += __shfl_down_sync(0xffffffffu, s, 1, 8);
    if (p == 0) gates[e] = s;
    __syncthreads();
    if (tid == 0) {
        float sc[NE], sel[NE];
        bool used[NE];
        for (int i = 0; i < NE; i++) {
            sc[i] = 1.f / (1.f + expf(-gates[i]));
            sel[i] = sc[i] + bias[i];
            used[i] = false;
        }
        int idx[TOPK]; float wv[TOPK]; float sum = 0.f;
        for (int k = 0; k < TOPK; k++) {
            int best = -1; float bv = -1e30f;
            for (int i = 0; i < NE; i++)
                if (!used[i] && sel[i] > bv) { bv = sel[i]; best = i; }
            used[best] = true; idx[k] = best; wv[k] = sc[best]; sum += sc[best];
        }
        float inv = ROUTE_SCALE / sum;
        for (int k = 0; k < TOPK; k++) {
            g_topk_idx[t * TOPK + k] = idx[k];
            g_topk_wt[t * TOPK + k] = wv[k] * inv;
            atomicAdd(&g_counts[idx[k]], 1);
        }
    }
}

// ---------------- L2: offsets + scatter ----------------
__global__ void __launch_bounds__(256) k_offsets_scatter() {
    int tid = threadIdx.x;
    if (tid == 0) {
        g_counts[NE] = T_TOK;
        int off = 0;
        for (int e = 0; e <= NE; e++) {
            g_offsets[e] = off;
            int tiles = (g_counts[e] + 127) >> 7;
            for (int j = 0; j < tiles; j++) g_tile_expert[(off >> 7) + j] = e;
            off += tiles << 7;
        }
        g_offsets[NE + 1] = off;
    }
    __syncthreads();
    for (int t = tid; t < T_TOK; t += 256) {
        for (int k = 0; k < TOPK; k++) {
            int e = g_topk_idx[t * TOPK + k];
            int pos = atomicAdd(&g_fill[e], 1);
            int r = g_offsets[e] + pos;
            g_row_token[r] = t;
            g_row_wt[r] = g_topk_wt[t * TOPK + k];
            g_token_rows[t * 9 + k] = r;
        }
        int r = g_offsets[NE] + t;
        g_row_token[r] = t;
        g_row_wt[r] = 1.f;
        g_token_rows[t * 9 + 8] = r;
    }
}

// ---------------- L3: gemm1 (256 thr, 8 warps 2m x 4n, warp 64x16) --------
// Stage 48KB: A 0..16K (128 rows), GH 16K, GL 24K, UH 32K, UL 40K
#define STG1 49152u
#define SMEM1_BYTES (3 * STG1)
__global__ void __launch_bounds__(256, 1) k_gemm1() {
    extern __shared__ char smem[];
    int e = g_tile_expert[blockIdx.x];
    if (e < 0) return;

    const int tid = threadIdx.x, wid = tid >> 5, lane = tid & 31;
    const int wm = (wid & 1) << 6;          // 0 or 64
    const int wn = (wid >> 1) << 4;         // 0,16,32,48
    const uint32_t sb = smem_u32(smem);
    const int col_base = blockIdx.y << 6;
    const int rb = blockIdx.x << 7;

    // ---- load assignment: 4 A chunks + 2 per weight plane
    uint32_t dA[4], dW[2];
    const __half *pA[4], *pGh[2], *pGl[2], *pUh[2], *pUl[2];
#pragma unroll
    for (int i = 0; i < 4; i++) {
        int idx = i * 256 + tid;
        int r = idx >> 3, c16 = idx & 7;
        dA[i] = SW((uint32_t)(r * 128 + c16 * 16));
        pA[i] = g_xh + (size_t)g_row_token[rb + r] * DHID + c16 * 8;
    }
#pragma unroll
    for (int i = 0; i < 2; i++) {
        int idx = i * 256 + tid;
        int r = idx >> 3, c16 = idx & 7;
        dW[i] = SW((uint32_t)(r * 128 + c16 * 16));
        size_t wb = ((size_t)e << 20) + (size_t)(col_base + r) * DHID + c16 * 8;
        pGh[i] = g_wgh + wb; pGl[i] = g_wgl + wb;
        pUh[i] = g_wuh + wb; pUl[i] = g_wul + wb;
    }

    int kadv = 0;
    auto issue = [&](int stg) {
        uint32_t base = sb + (uint32_t)stg * STG1;
#pragma unroll
        for (int i = 0; i < 4; i++) cpa16(base + dA[i], pA[i] + kadv);
#pragma unroll
        for (int i = 0; i < 2; i++) {
            cpa16(base + 16384u + dW[i], pGh[i] + kadv);
            cpa16(base + 24576u + dW[i], pGl[i] + kadv);
            cpa16(base + 32768u + dW[i], pUh[i] + kadv);
            cpa16(base + 40960u + dW[i], pUl[i] + kadv);
        }
        CPA_COMMIT();
        kadv += 64;
    };

    // ---- ldsm addressing
    const int lr = lane & 15;
    const uint32_t hb = (uint32_t)((lane >> 4) << 4);
    uint32_t arow[4], amask[4];
#pragma unroll
    for (int mt = 0; mt < 4; mt++) {
        int rr = wm + (mt << 4) + lr;
        arow[mt] = (uint32_t)(rr * 128);
        amask[mt] = (uint32_t)((rr & 7) << 4);
    }
    const int brr = wn + lr;
    const uint32_t brow = (uint32_t)(brr * 128);
    const uint32_t bmask = (uint32_t)((brr & 7) << 4);

    float ag[4][2][4] = {}, au[4][2][4] = {};

    issue(0); issue(1);
    const int NK = DHID / 64;
    int stg = 2;
    for (int kc = 0; kc < NK; kc++) {
        if (kc + 1 == NK) { CPA_WAIT0(); } else { CPA_WAIT1(); }
        __syncthreads();
        if (kc + 2 < NK) { issue(stg); stg = (stg == 2) ? 0 : stg + 1; }
        uint32_t base = sb + (uint32_t)((kc % 3)) * STG1;
#pragma unroll
        for (int ks = 0; ks < 4; ks++) {
            uint32_t kb = (uint32_t)(ks << 5) | hb;
            uint32_t ah[4][4];
#pragma unroll
            for (int mt = 0; mt < 4; mt++)
                ldsm4(ah[mt], base + arow[mt] + (kb ^ amask[mt]));
            uint32_t boff = brow + (kb ^ bmask);
            uint32_t gh[4], gl[4], uh[4], ul[4];
            ldsm4(gh, base + 16384u + boff);
            ldsm4(gl, base + 24576u + boff);
            ldsm4(uh, base + 32768u + boff);
            ldsm4(ul, base + 40960u + boff);
#pragma unroll
            for (int mt = 0; mt < 4; mt++) {
                mma_f16(ag[mt][0], ah[mt], gh[0], gh[2]);
                mma_f16(ag[mt][0], ah[mt], gl[0], gl[2]);
                mma_f16(ag[mt][1], ah[mt], gh[1], gh[3]);
                mma_f16(ag[mt][1], ah[mt], gl[1], gl[3]);
                mma_f16(au[mt][0], ah[mt], uh[0], uh[2]);
                mma_f16(au[mt][0], ah[mt], ul[0], ul[2]);
                mma_f16(au[mt][1], ah[mt], uh[1], uh[3]);
                mma_f16(au[mt][1], ah[mt], ul[1], ul[3]);
            }
        }
    }

    // epilogue: SwiGLU -> fp16 H
#pragma unroll
    for (int mt = 0; mt < 4; mt++) {
        int r0 = rb + wm + (mt << 4) + (lane >> 2);
#pragma unroll
        for (int n8 = 0; n8 < 2; n8++) {
            int c = col_base + wn + (n8 << 3) + ((lane & 3) << 1);
#pragma unroll
            for (int hf = 0; hf < 2; hf++) {
                int rr = r0 + hf * 8;
                float g0 = ag[mt][n8][hf * 2 + 0], g1 = ag[mt][n8][hf * 2 + 1];
                float u0 = au[mt][n8][hf * 2 + 0], u1 = au[mt][n8][hf * 2 + 1];
                float h0 = g0 * u0 / (1.f + __expf(-g0));
                float h1 = g1 * u1 / (1.f + __expf(-g1));
                *(__half2*)&g_Hh[(size_t)rr * NI + c] = __floats2half2_rn(h0, h1);
            }
        }
    }
}

// ---------------- L4: gemm2 (256 thr, 8 warps 2m x 4n, warp 64x32) --------
// Stage 48KB: A 0..16K, BH 16K..32K, BL 32K..48K
#define STG2 49152u
#define SMEM2_BYTES (3 * STG2)
__global__ void __launch_bounds__(256, 1) k_gemm2() {
    extern __shared__ char smem[];
    int e = g_tile_expert[blockIdx.x];
    if (e < 0) return;

    const int tid = threadIdx.x, wid = tid >> 5, lane = tid & 31;
    const int wm = (wid & 1) << 6;          // 0 or 64
    const int wn = (wid >> 1) << 5;         // 0,32,64,96
    const uint32_t sb = smem_u32(smem);
    const int col_base = blockIdx.y << 7;
    const int rb = blockIdx.x << 7;

    uint32_t dA[4];
    const __half *pA[4], *pBh[4], *pBl[4];
#pragma unroll
    for (int i = 0; i < 4; i++) {
        int idx = i * 256 + tid;
        int r = idx >> 3, c16 = idx & 7;
        dA[i] = SW((uint32_t)(r * 128 + c16 * 16));
        pA[i] = g_Hh + (size_t)(rb + r) * NI + c16 * 8;
        size_t wb = ((size_t)e << 20) + (size_t)(col_base + r) * NI + c16 * 8;
        pBh[i] = g_wdh + wb;
        pBl[i] = g_wdl + wb;
    }

    int kadv = 0;
    auto issue = [&](int stg) {
        uint32_t base = sb + (uint32_t)stg * STG2;
#pragma unroll
        for (int i = 0; i < 4; i++) {
            cpa16(base + dA[i], pA[i] + kadv);
            cpa16(base + 16384u + dA[i], pBh[i] + kadv);
            cpa16(base + 32768u + dA[i], pBl[i] + kadv);
        }
        CPA_COMMIT();
        kadv += 64;
    };

    const int lr = lane & 15;
    const uint32_t hb = (uint32_t)((lane >> 4) << 4);
    uint32_t arow[4], amask[4];
#pragma unroll
    for (int mt = 0; mt < 4; mt++) {
        int rr = wm + (mt << 4) + lr;
        arow[mt] = (uint32_t)(rr * 128);
        amask[mt] = (uint32_t)((rr & 7) << 4);
    }
    uint32_t brow[2], bmask[2];
#pragma unroll
    for (int nt = 0; nt < 2; nt++) {
        int rr = wn + (nt << 4) + lr;
        brow[nt] = (uint32_t)(rr * 128);
        bmask[nt] = (uint32_t)((rr & 7) << 4);
    }

    float ad[4][4][4] = {};

    issue(0); issue(1);
    const int NK = NI / 64;
    int stg = 2;
    for (int kc = 0; kc < NK; kc++) {
        if (kc + 1 == NK) { CPA_WAIT0(); } else { CPA_WAIT1(); }
        __syncthreads();
        if (kc + 2 < NK) { issue(stg); stg = (stg == 2) ? 0 : stg + 1; }
        uint32_t base = sb + (uint32_t)((kc % 3)) * STG2;
#pragma unroll
        for (int ks = 0; ks < 4; ks++) {
            uint32_t kb = (uint32_t)(ks << 5) | hb;
            uint32_t ah[4][4];
#pragma unroll
            for (int mt = 0; mt < 4; mt++)
                ldsm4(ah[mt], base + arow[mt] + (kb ^ amask[mt]));
#pragma unroll
            for (int nt = 0; nt < 2; nt++) {
                uint32_t boff = kb ^ bmask[nt];
                uint32_t bh[4], bl[4];
                ldsm4(bh, base + 16384u + brow[nt] + boff);
                ldsm4(bl, base + 32768u + brow[nt] + boff);
#pragma unroll
                for (int mt = 0; mt < 4; mt++) {
                    mma_f16(ad[mt][nt * 2 + 0], ah[mt], bh[0], bh[2]);
                    mma_f16(ad[mt][nt * 2 + 0], ah[mt], bl[0], bl[2]);
                    mma_f16(ad[mt][nt * 2 + 1], ah[mt], bh[1], bh[3]);
                    mma_f16(ad[mt][nt * 2 + 1], ah[mt], bl[1], bl[3]);
                }
            }
        }
    }

#pragma unroll
    for (int mt = 0; mt < 4; mt++) {
        int r0 = rb + wm + (mt << 4) + (lane >> 2);
        float w0 = g_row_wt[r0], w1 = g_row_wt[r0 + 8];
#pragma unroll
        for (int j = 0; j < 4; j++) {
            int c = col_base + wn + ((j >> 1) << 4) + ((j & 1) << 3) + ((lane & 3) << 1);
            float2 o0 = make_float2(ad[mt][j][0] * w0, ad[mt][j][1] * w0);
            *(float2*)&g_Y[(size_t)r0 * DHID + c] = o0;
            float2 o1 = make_float2(ad[mt][j][2] * w1, ad[mt][j][3] * w1);
            *(float2*)&g_Y[(size_t)(r0 + 8) * DHID + c] = o1;
        }
    }
}

// ---------------- L5: combine ----------------
__global__ void __launch_bounds__(256) k_combine(float* __restrict__ out) {
    int t = blockIdx.x, tid = threadIdx.x;
    int d0 = tid << 2;
    float4 acc = make_float4(0.f, 0.f, 0.f, 0.f);
#pragma unroll
    for (int k = 0; k < 9; k++) {
        int r = g_token_rows[t * 9 + k];
        float4 v = *(const float4*)&g_Y[(size_t)r * DHID + d0];
        acc.x += v.x; acc.y += v.y; acc.z += v.z; acc.w += v.w;
    }
    *(float4*)&out[(size_t)t * DHID + d0] = acc;
}

// ---------------- launch ----------------
extern "C" void kernel_launch(void* const* d_in, const int* in_sizes, int n_in,
                              void* d_out, int out_size) {
    const float* x       = (const float*)d_in[0];
    const float* gate_w  = (const float*)d_in[1];
    const float* ebias   = (const float*)d_in[2];
    const float* w_gate  = (const float*)d_in[3];
    const float* w_up    = (const float*)d_in[4];
    const float* w_down  = (const float*)d_in[5];
    const float* sh_gate = (const float*)d_in[6];
    const float* sh_up   = (const float*)d_in[7];
    const float* sh_down = (const float*)d_in[8];
    float* out = (float*)d_out;

    cudaFuncSetAttribute(k_gemm1, cudaFuncAttributeMaxDynamicSharedMemorySize, SMEM1_BYTES);
    cudaFuncSetAttribute(k_gemm2, cudaFuncAttributeMaxDynamicSharedMemorySize, SMEM2_BYTES);

    __half *xh, *xl, *wgh, *wgl, *wuh, *wul, *wdh, *wdl;
    cudaGetSymbolAddress((void**)&xh, g_xh);  cudaGetSymbolAddress((void**)&xl, g_xl);
    cudaGetSymbolAddress((void**)&wgh, g_wgh); cudaGetSymbolAddress((void**)&wgl, g_wgl);
    cudaGetSymbolAddress((void**)&wuh, g_wuh); cudaGetSymbolAddress((void**)&wul, g_wul);
    cudaGetSymbolAddress((void**)&wdh, g_wdh); cudaGetSymbolAddress((void**)&wdl, g_wdl);

    const size_t SHOFF = (size_t)16 * WSZ;
    const int BX = 1024, BW = 16384, BS = 1024;
    SplitArgs sa;
    sa.src[0] = x;       sa.hi[0] = xh;          sa.lo[0] = xl;
    sa.src[1] = w_gate;  sa.hi[1] = wgh;         sa.lo[1] = wgl;
    sa.src[2] = sh_gate; sa.hi[2] = wgh + SHOFF; sa.lo[2] = wgl + SHOFF;
    sa.src[3] = w_up;    sa.hi[3] = wuh;         sa.lo[3] = wul;
    sa.src[4] = sh_up;   sa.hi[4] = wuh + SHOFF; sa.lo[4] = wul + SHOFF;
    sa.src[5] = w_down;  sa.hi[5] = wdh;         sa.lo[5] = wdl;
    sa.src[6] = sh_down; sa.hi[6] = wdh + SHOFF; sa.lo[6] = wdl + SHOFF;
    int acc = 0;
    const int bc[7] = {BX, BW, BS, BW, BS, BW, BS};
    for (int i = 0; i < 7; i++) { acc += bc[i]; sa.blk_end[i] = acc; }
    sa.split_blocks = acc;
    int init_blocks = (ROWS_CAP + 255) / 256;

    k_split_all<<<acc + init_blocks, 256>>>(sa);                  // idx 0
    k_route<<<T_TOK, 128>>>(x, gate_w, ebias);                    // idx 1
    k_offsets_scatter<<<1, 256>>>();                              // idx 2
    k_gemm1<<<dim3(ROW_TILES, NI / 64), 256, SMEM1_BYTES>>>();    // idx 3 <- ncu
    k_gemm2<<<dim3(ROW_TILES, DHID / 128), 256, SMEM2_BYTES>>>(); // idx 4
    k_combine<<<T_TOK, 256>>>(out);                               // idx 5
}

// round 13
// speedup vs baseline: 1.6667x; 1.6667x over previous
#include <cuda_runtime.h>
#include <cuda_fp16.h>
#include <math.h>
#include <stdint.h>

#define T_TOK 1024
#define DHID 1024
#define NE 16
#define TOPK 8
#define NI 1024
#define ROUTE_SCALE 2.826f

#define ROW_TILES 88
#define ROWS_CAP (ROW_TILES * 128)
#define WSZ (1u << 20)

#define SW(o) ((o) ^ (((o) >> 3) & 0x70))

// ---------------- scratch ----------------
__device__ __half g_xh[T_TOK * DHID];
__device__ __half g_wgh[17 * WSZ];
__device__ __half g_wuh[17 * WSZ];
__device__ __half g_wdh[17 * WSZ];
__device__ __half g_Hh[(size_t)ROWS_CAP * NI];
__device__ float  g_Y[(size_t)ROWS_CAP * DHID];
__device__ int    g_row_token[ROWS_CAP];
__device__ float  g_row_wt[ROWS_CAP];
__device__ int    g_tile_expert[ROW_TILES];
__device__ int    g_token_rows[T_TOK * 9];
__device__ int    g_counts[NE + 1];
__device__ int    g_fill[NE + 1];
__device__ int    g_offsets[NE + 2];
__device__ int    g_topk_idx[T_TOK * TOPK];
__device__ float  g_topk_wt[T_TOK * TOPK];

// ---------------- helpers ----------------
__device__ __forceinline__ uint32_t smem_u32(const void* p) {
    uint32_t a;
    asm("{ .reg .u64 t; cvta.to.shared.u64 t, %1; cvt.u32.u64 %0, t; }" : "=r"(a) : "l"(p));
    return a;
}
__device__ __forceinline__ void ldsm4(uint32_t (&r)[4], uint32_t addr) {
    asm volatile("ldmatrix.sync.aligned.m8n8.x4.shared.b16 {%0,%1,%2,%3}, [%4];"
                 : "=r"(r[0]), "=r"(r[1]), "=r"(r[2]), "=r"(r[3]) : "r"(addr));
}
__device__ __forceinline__ void mma_f16(float (&d)[4], const uint32_t (&a)[4],
                                        uint32_t b0, uint32_t b1) {
    asm volatile("mma.sync.aligned.m16n8k16.row.col.f32.f16.f16.f32 "
                 "{%0,%1,%2,%3}, {%4,%5,%6,%7}, {%8,%9}, {%0,%1,%2,%3};"
                 : "+f"(d[0]), "+f"(d[1]), "+f"(d[2]), "+f"(d[3])
                 : "r"(a[0]), "r"(a[1]), "r"(a[2]), "r"(a[3]), "r"(b0), "r"(b1));
}
__device__ __forceinline__ void cpa16(uint32_t dst, const void* src) {
    asm volatile("cp.async.cg.shared.global [%0], [%1], 16;" :: "r"(dst), "l"(src));
}
#define CPA_COMMIT() asm volatile("cp.async.commit_group;" ::: "memory")
#define CPA_WAIT1()  asm volatile("cp.async.wait_group 1;" ::: "memory")
#define CPA_WAIT0()  asm volatile("cp.async.wait_group 0;" ::: "memory")

// ---------------- L0: fp32 -> fp16 convert + init ----------------
struct SplitArgs {
    const float* src[7];
    __half* hi[7];
    int blk_end[7];
    int split_blocks;
};
__global__ void __launch_bounds__(256) k_split_all(SplitArgs a) {
    int b = blockIdx.x;
    if (b >= a.split_blocks) {
        int i = (b - a.split_blocks) * 256 + threadIdx.x;
        if (i < ROWS_CAP) { g_row_token[i] = 0; g_row_wt[i] = 0.f; }
        if (i < ROW_TILES) g_tile_expert[i] = -1;
        if (i < NE + 1) { g_counts[i] = 0; g_fill[i] = 0; }
        return;
    }
    int s = 0;
    while (b >= a.blk_end[s]) s++;
    int base = s ? a.blk_end[s - 1] : 0;
    size_t i = ((size_t)(b - base) * 256 + threadIdx.x) << 3;
    float4 v0 = *(const float4*)(a.src[s] + i);
    float4 v1 = *(const float4*)(a.src[s] + i + 4);
    uint4 hp;
    __half2 p0 = __floats2half2_rn(v0.x, v0.y);
    __half2 p1 = __floats2half2_rn(v0.z, v0.w);
    __half2 p2 = __floats2half2_rn(v1.x, v1.y);
    __half2 p3 = __floats2half2_rn(v1.z, v1.w);
    hp.x = *(uint32_t*)&p0; hp.y = *(uint32_t*)&p1;
    hp.z = *(uint32_t*)&p2; hp.w = *(uint32_t*)&p3;
    *(uint4*)&a.hi[s][i] = hp;
}

// ---------------- L1: routing ----------------
__global__ void __launch_bounds__(128) k_route(const float* __restrict__ x,
                                               const float* __restrict__ gw,
                                               const float* __restrict__ bias) {
    __shared__ float xs[DHID];
    __shared__ float gates[NE];
    int t = blockIdx.x, tid = threadIdx.x;
    for (int i = tid; i < DHID; i += 128) xs[i] = x[(size_t)t * DHID + i];
    __syncthreads();
    int e = tid >> 3, p = tid & 7;
    const float* w = gw + e * DHID + p * 128;
    const float* xv = xs + p * 128;
    float s = 0.f;
#pragma unroll 8
    for (int d = 0; d < 128; d++) s += xv[d] * w[d];
    s += __shfl_down_sync(0xffffffffu, s, 4, 8);
    s += __shfl_down_sync(0xffffffffu, s, 2, 8);
    s += __shfl_down_sync(0xffffffffu, s, 1, 8);
    if (p == 0) gates[e] = s;
    __syncthreads();
    if (tid == 0) {
        float sc[NE], sel[NE];
        bool used[NE];
        for (int i = 0; i < NE; i++) {
            sc[i] = 1.f / (1.f + expf(-gates[i]));
            sel[i] = sc[i] + bias[i];
            used[i] = false;
        }
        int idx[TOPK]; float wv[TOPK]; float sum = 0.f;
        for (int k = 0; k < TOPK; k++) {
            int best = -1; float bv = -1e30f;
            for (int i = 0; i < NE; i++)
                if (!used[i] && sel[i] > bv) { bv = sel[i]; best = i; }
            used[best] = true; idx[k] = best; wv[k] = sc[best]; sum += sc[best];
        }
        float inv = ROUTE_SCALE / sum;
        for (int k = 0; k < TOPK; k++) {
            g_topk_idx[t * TOPK + k] = idx[k];
            g_topk_wt[t * TOPK + k] = wv[k] * inv;
            atomicAdd(&g_counts[idx[k]], 1);
        }
    }
}

// ---------------- L2: offsets + scatter ----------------
__global__ void __launch_bounds__(256) k_offsets_scatter() {
    int tid = threadIdx.x;
    if (tid == 0) {
        g_counts[NE] = T_TOK;
        int off = 0;
        for (int e = 0; e <= NE; e++) {
            g_offsets[e] = off;
            int tiles = (g_counts[e] + 127) >> 7;
            for (int j = 0; j < tiles; j++) g_tile_expert[(off >> 7) + j] = e;
            off += tiles << 7;
        }
        g_offsets[NE + 1] = off;
    }
    __syncthreads();
    for (int t = tid; t < T_TOK; t += 256) {
        for (int k = 0; k < TOPK; k++) {
            int e = g_topk_idx[t * TOPK + k];
            int pos = atomicAdd(&g_fill[e], 1);
            int r = g_offsets[e] + pos;
            g_row_token[r] = t;
            g_row_wt[r] = g_topk_wt[t * TOPK + k];
            g_token_rows[t * 9 + k] = r;
        }
        int r = g_offsets[NE] + t;
        g_row_token[r] = t;
        g_row_wt[r] = 1.f;
        g_token_rows[t * 9 + 8] = r;
    }
}

// ---------------- L3: gemm1 (512 thr, single-term fp16) -------------------
// Stage 32KB: A 0..16K (128x128B), G 16K..24K, U 24K..32K
#define STG1 32768u
#define SMEM1_BYTES (3 * STG1)
__global__ void __launch_bounds__(512, 1) k_gemm1() {
    extern __shared__ char smem[];
    int e = g_tile_expert[blockIdx.x];
    if (e < 0) return;

    const int tid = threadIdx.x, wid = tid >> 5, lane = tid & 31;
    const int wm = (wid & 3) << 5;          // 0..96
    const int wn = (wid >> 2) << 4;         // 0,16,32,48
    const uint32_t sb = smem_u32(smem);
    const int col_base = blockIdx.y << 6;
    const int rb = blockIdx.x << 7;

    // loads: thread covers A rows r, r+64 and W row r (r=tid>>3), chunk tid&7
    const int r = tid >> 3;
    const int c8 = (tid & 7) << 3;
    const uint32_t dA = SW((uint32_t)(r * 128 + (c8 << 1)));
    const __half* pA0 = g_xh + (size_t)g_row_token[rb + r] * DHID + c8;
    const __half* pA1 = g_xh + (size_t)g_row_token[rb + r + 64] * DHID + c8;
    const size_t wbase = ((size_t)e << 20) + (size_t)(col_base + r) * DHID + c8;
    const __half* pG = g_wgh + wbase;
    const __half* pU = g_wuh + wbase;

    int kadv = 0;
    auto issue = [&](int stg) {
        uint32_t base = sb + (uint32_t)stg * STG1;
        cpa16(base + dA, pA0 + kadv);
        cpa16(base + 8192u + dA, pA1 + kadv);
        cpa16(base + 16384u + dA, pG + kadv);
        cpa16(base + 24576u + dA, pU + kadv);
        CPA_COMMIT();
        kadv += 64;
    };

    const int lr = lane & 15;
    const uint32_t hb = (uint32_t)((lane >> 4) << 4);
    uint32_t arow[2], amask[2];
#pragma unroll
    for (int mt = 0; mt < 2; mt++) {
        int rr = wm + (mt << 4) + lr;
        arow[mt] = (uint32_t)(rr * 128);
        amask[mt] = (uint32_t)((rr & 7) << 4);
    }
    const int brr = wn + lr;
    const uint32_t brow = (uint32_t)(brr * 128);
    const uint32_t bmask = (uint32_t)((brr & 7) << 4);

    float ag[2][2][4] = {}, au[2][2][4] = {};

    issue(0); issue(1);
    const int NK = DHID / 64;
    int stg = 2;
    for (int kc = 0; kc < NK; kc++) {
        if (kc + 1 == NK) { CPA_WAIT0(); } else { CPA_WAIT1(); }
        __syncthreads();
        if (kc + 2 < NK) { issue(stg); stg = (stg == 2) ? 0 : stg + 1; }
        uint32_t base = sb + (uint32_t)((kc % 3)) * STG1;
#pragma unroll
        for (int ks = 0; ks < 4; ks++) {
            uint32_t kb = (uint32_t)(ks << 5) | hb;
            uint32_t ah[2][4];
#pragma unroll
            for (int mt = 0; mt < 2; mt++)
                ldsm4(ah[mt], base + arow[mt] + (kb ^ amask[mt]));
            uint32_t boff = brow + (kb ^ bmask);
            uint32_t gh[4], uh[4];
            ldsm4(gh, base + 16384u + boff);
            ldsm4(uh, base + 24576u + boff);
#pragma unroll
            for (int mt = 0; mt < 2; mt++) {
                mma_f16(ag[mt][0], ah[mt], gh[0], gh[2]);
                mma_f16(ag[mt][1], ah[mt], gh[1], gh[3]);
                mma_f16(au[mt][0], ah[mt], uh[0], uh[2]);
                mma_f16(au[mt][1], ah[mt], uh[1], uh[3]);
            }
        }
    }

    // epilogue: SwiGLU -> fp16 H
#pragma unroll
    for (int mt = 0; mt < 2; mt++) {
        int r0 = rb + wm + (mt << 4) + (lane >> 2);
#pragma unroll
        for (int n8 = 0; n8 < 2; n8++) {
            int c = col_base + wn + (n8 << 3) + ((lane & 3) << 1);
#pragma unroll
            for (int hf = 0; hf < 2; hf++) {
                int rr = r0 + hf * 8;
                float g0 = ag[mt][n8][hf * 2 + 0], g1 = ag[mt][n8][hf * 2 + 1];
                float u0 = au[mt][n8][hf * 2 + 0], u1 = au[mt][n8][hf * 2 + 1];
                float h0 = g0 * u0 / (1.f + __expf(-g0));
                float h1 = g1 * u1 / (1.f + __expf(-g1));
                *(__half2*)&g_Hh[(size_t)rr * NI + c] = __floats2half2_rn(h0, h1);
            }
        }
    }
}

// ---------------- L4: gemm2 (512 thr, single-term fp16) -------------------
// Stage 32KB: A 0..16K, B 16K..32K
#define STG2 32768u
#define SMEM2_BYTES (3 * STG2)
__global__ void __launch_bounds__(512, 1) k_gemm2() {
    extern __shared__ char smem[];
    int e = g_tile_expert[blockIdx.x];
    if (e < 0) return;

    const int tid = threadIdx.x, wid = tid >> 5, lane = tid & 31;
    const int wm = (wid & 3) << 5;
    const int wn = (wid >> 2) << 5;         // 0,32,64,96
    const uint32_t sb = smem_u32(smem);
    const int col_base = blockIdx.y << 7;
    const int rb = blockIdx.x << 7;

    const int r = tid >> 3;
    const int c8 = (tid & 7) << 3;
    const uint32_t dA = SW((uint32_t)(r * 128 + (c8 << 1)));
    const __half* pA0 = g_Hh + (size_t)(rb + r) * NI + c8;
    const __half* pA1 = g_Hh + (size_t)(rb + r + 64) * NI + c8;
    const size_t wb0 = ((size_t)e << 20) + (size_t)(col_base + r) * NI + c8;
    const size_t wb1 = ((size_t)e << 20) + (size_t)(col_base + r + 64) * NI + c8;
    const __half* pB0 = g_wdh + wb0;
    const __half* pB1 = g_wdh + wb1;

    int kadv = 0;
    auto issue = [&](int stg) {
        uint32_t base = sb + (uint32_t)stg * STG2;
        cpa16(base + dA, pA0 + kadv);
        cpa16(base + 8192u + dA, pA1 + kadv);
        cpa16(base + 16384u + dA, pB0 + kadv);
        cpa16(base + 24576u + dA, pB1 + kadv);
        CPA_COMMIT();
        kadv += 64;
    };

    const int lr = lane & 15;
    const uint32_t hb = (uint32_t)((lane >> 4) << 4);
    uint32_t arow[2], amask[2];
#pragma unroll
    for (int mt = 0; mt < 2; mt++) {
        int rr = wm + (mt << 4) + lr;
        arow[mt] = (uint32_t)(rr * 128);
        amask[mt] = (uint32_t)((rr & 7) << 4);
    }
    uint32_t brow[2], bmask[2];
#pragma unroll
    for (int nt = 0; nt < 2; nt++) {
        int rr = wn + (nt << 4) + lr;
        brow[nt] = (uint32_t)(rr * 128);
        bmask[nt] = (uint32_t)((rr & 7) << 4);
    }

    float ad[2][4][4] = {};

    issue(0); issue(1);
    const int NK = NI / 64;
    int stg = 2;
    for (int kc = 0; kc < NK; kc++) {
        if (kc + 1 == NK) { CPA_WAIT0(); } else { CPA_WAIT1(); }
        __syncthreads();
        if (kc + 2 < NK) { issue(stg); stg = (stg == 2) ? 0 : stg + 1; }
        uint32_t base = sb + (uint32_t)((kc % 3)) * STG2;
#pragma unroll
        for (int ks = 0; ks < 4; ks++) {
            uint32_t kb = (uint32_t)(ks << 5) | hb;
            uint32_t ah[2][4];
#pragma unroll
            for (int mt = 0; mt < 2; mt++)
                ldsm4(ah[mt], base + arow[mt] + (kb ^ amask[mt]));
#pragma unroll
            for (int nt = 0; nt < 2; nt++) {
                uint32_t boff = brow[nt] + (kb ^ bmask[nt]);
                uint32_t bh[4];
                ldsm4(bh, base + 16384u + boff);
#pragma unroll
                for (int mt = 0; mt < 2; mt++) {
                    mma_f16(ad[mt][nt * 2 + 0], ah[mt], bh[0], bh[2]);
                    mma_f16(ad[mt][nt * 2 + 1], ah[mt], bh[1], bh[3]);
                }
            }
        }
    }

#pragma unroll
    for (int mt = 0; mt < 2; mt++) {
        int r0 = rb + wm + (mt << 4) + (lane >> 2);
        float w0 = g_row_wt[r0], w1 = g_row_wt[r0 + 8];
#pragma unroll
        for (int nt = 0; nt < 2; nt++) {
#pragma unroll
            for (int n8 = 0; n8 < 2; n8++) {
                int j = nt * 2 + n8;
                int c = col_base + wn + (nt << 4) + (n8 << 3) + ((lane & 3) << 1);
                float2 o0 = make_float2(ad[mt][j][0] * w0, ad[mt][j][1] * w0);
                *(float2*)&g_Y[(size_t)r0 * DHID + c] = o0;
                float2 o1 = make_float2(ad[mt][j][2] * w1, ad[mt][j][3] * w1);
                *(float2*)&g_Y[(size_t)(r0 + 8) * DHID + c] = o1;
            }
        }
    }
}

// ---------------- L5: combine ----------------
__global__ void __launch_bounds__(256) k_combine(float* __restrict__ out) {
    int t = blockIdx.x, tid = threadIdx.x;
    int d0 = tid << 2;
    float4 acc = make_float4(0.f, 0.f, 0.f, 0.f);
#pragma unroll
    for (int k = 0; k < 9; k++) {
        int r = g_token_rows[t * 9 + k];
        float4 v = *(const float4*)&g_Y[(size_t)r * DHID + d0];
        acc.x += v.x; acc.y += v.y; acc.z += v.z; acc.w += v.w;
    }
    *(float4*)&out[(size_t)t * DHID + d0] = acc;
}

// ---------------- launch ----------------
extern "C" void kernel_launch(void* const* d_in, const int* in_sizes, int n_in,
                              void* d_out, int out_size) {
    const float* x       = (const float*)d_in[0];
    const float* gate_w  = (const float*)d_in[1];
    const float* ebias   = (const float*)d_in[2];
    const float* w_gate  = (const float*)d_in[3];
    const float* w_up    = (const float*)d_in[4];
    const float* w_down  = (const float*)d_in[5];
    const float* sh_gate = (const float*)d_in[6];
    const float* sh_up   = (const float*)d_in[7];
    const float* sh_down = (const float*)d_in[8];
    float* out = (float*)d_out;

    cudaFuncSetAttribute(k_gemm1, cudaFuncAttributeMaxDynamicSharedMemorySize, SMEM1_BYTES);
    cudaFuncSetAttribute(k_gemm2, cudaFuncAttributeMaxDynamicSharedMemorySize, SMEM2_BYTES);

    __half *xh, *wgh, *wuh, *wdh;
    cudaGetSymbolAddress((void**)&xh, g_xh);
    cudaGetSymbolAddress((void**)&wgh, g_wgh);
    cudaGetSymbolAddress((void**)&wuh, g_wuh);
    cudaGetSymbolAddress((void**)&wdh, g_wdh);

    const size_t SHOFF = (size_t)16 * WSZ;
    // 8 floats per thread: blocks = elems/2048
    const int BX = 512, BW = 8192, BS = 512;
    SplitArgs sa;
    sa.src[0] = x;       sa.hi[0] = xh;
    sa.src[1] = w_gate;  sa.hi[1] = wgh;
    sa.src[2] = sh_gate; sa.hi[2] = wgh + SHOFF;
    sa.src[3] = w_up;    sa.hi[3] = wuh;
    sa.src[4] = sh_up;   sa.hi[4] = wuh + SHOFF;
    sa.src[5] = w_down;  sa.hi[5] = wdh;
    sa.src[6] = sh_down; sa.hi[6] = wdh + SHOFF;
    int acc = 0;
    const int bc[7] = {BX, BW, BS, BW, BS, BW, BS};
    for (int i = 0; i < 7; i++) { acc += bc[i]; sa.blk_end[i] = acc; }
    sa.split_blocks = acc;
    int init_blocks = (ROWS_CAP + 255) / 256;

    k_split_all<<<acc + init_blocks, 256>>>(sa);                  // idx 0
    k_route<<<T_TOK, 128>>>(x, gate_w, ebias);                    // idx 1
    k_offsets_scatter<<<1, 256>>>();                              // idx 2
    k_gemm1<<<dim3(ROW_TILES, NI / 64), 512, SMEM1_BYTES>>>();    // idx 3 <- ncu
    k_gemm2<<<dim3(ROW_TILES, DHID / 128), 512, SMEM2_BYTES>>>(); // idx 4
    k_combine<<<T_TOK, 256>>>(out);                               // idx 5
}